// round 1
// baseline (speedup 1.0000x reference)
#include <cuda_runtime.h>
#include <cuda_bf16.h>

#define N_NODES 100000
#define N_EDGES 1600000
#define C 64

// Scratch: transformed features h = x @ W, and CSR row pointers.
__device__ float g_h[(size_t)N_NODES * C];
__device__ int g_row_ptr[N_NODES + 1];

// ---------------------------------------------------------------------------
// Kernel 1: h = x @ W  (row tile of 64 per block, W + x tile in shared,
// packed f32x2 FMA accumulation)
// ---------------------------------------------------------------------------
__global__ __launch_bounds__(256) void gemm64_kernel(const float* __restrict__ x,
                                                     const float* __restrict__ w) {
    __shared__ float xs[64 * 65];   // padded: bank-conflict-free xs[r*65+k] reads
    __shared__ float ws[64 * 64];

    const int tid = threadIdx.x;
    const long row0 = (long)blockIdx.x * 64;

    // Load W (64x64 = 1024 float4) cooperatively.
    const float4* w4 = (const float4*)w;
    float4* ws4 = (float4*)ws;
#pragma unroll
    for (int i = 0; i < 4; i++) ws4[tid + i * 256] = w4[tid + i * 256];

    // Load x tile (64 rows x 16 float4), scalar stores into padded smem.
#pragma unroll
    for (int i = 0; i < 4; i++) {
        int idx = tid + i * 256;          // 0..1023
        int r = idx >> 4, c4 = idx & 15;
        long gr = row0 + r;
        float4 v = make_float4(0.f, 0.f, 0.f, 0.f);
        if (gr < N_NODES) v = ((const float4*)x)[gr * 16 + c4];
        float* dst = xs + r * 65 + c4 * 4;
        dst[0] = v.x; dst[1] = v.y; dst[2] = v.z; dst[3] = v.w;
    }
    __syncthreads();

    // Each thread: one row (r), 16 output columns (cc*16 .. cc*16+15).
    // Warps share cc -> W loads are broadcast (conflict-free).
    const int r = tid & 63;
    const int cc = tid >> 6;

    unsigned long long acc[8];
#pragma unroll
    for (int j = 0; j < 8; j++) acc[j] = 0ull;   // {0.f, 0.f} packed

#pragma unroll
    for (int k = 0; k < 64; k++) {
        float xv = xs[r * 65 + k];
        unsigned long long x2;
        asm("mov.b64 %0, {%1, %1};" : "=l"(x2) : "r"(__float_as_uint(xv)));
        const unsigned long long* wr =
            (const unsigned long long*)(ws + k * 64 + cc * 16);
#pragma unroll
        for (int j = 0; j < 8; j++) {
            asm("fma.rn.f32x2 %0, %1, %2, %0;" : "+l"(acc[j]) : "l"(x2), "l"(wr[j]));
        }
    }

    long gr = row0 + r;
    if (gr < N_NODES) {
        unsigned long long* op = (unsigned long long*)(g_h + gr * 64 + cc * 16);
#pragma unroll
        for (int j = 0; j < 8; j++) op[j] = acc[j];
    }
}

// ---------------------------------------------------------------------------
// Kernel 2: row_ptr[n] = lower_bound(row_index, n)  (row_index is sorted)
// ---------------------------------------------------------------------------
__global__ __launch_bounds__(256) void rowptr_kernel(const int* __restrict__ row_index) {
    int n = blockIdx.x * blockDim.x + threadIdx.x;
    if (n > N_NODES) return;
    int lo = 0, hi = N_EDGES;
    while (lo < hi) {
        int mid = (lo + hi) >> 1;
        if (row_index[mid] < n) lo = mid + 1;
        else hi = mid;
    }
    g_row_ptr[n] = lo;
}

// ---------------------------------------------------------------------------
// Kernel 3: warp-per-node segment sum over gathered h rows, fused
// degree scale + bias. No atomics (CSR segments).
// Each lane owns 2 consecutive feature columns via float2.
// ---------------------------------------------------------------------------
__global__ __launch_bounds__(256) void agg_kernel(const int* __restrict__ column_index,
                                                  const float* __restrict__ degrees,
                                                  const float* __restrict__ bias,
                                                  float* __restrict__ out) {
    const int gwarp = (blockIdx.x * blockDim.x + threadIdx.x) >> 5;
    const int lane = threadIdx.x & 31;
    if (gwarp >= N_NODES) return;

    const int start = g_row_ptr[gwarp];
    const int end = g_row_ptr[gwarp + 1];

    float ax = 0.f, ay = 0.f;

    int e = start;
    // unroll-by-2 for a bit of MLP on the dependent idx->gather chain
    for (; e + 1 < end; e += 2) {
        int s0 = __ldg(&column_index[e]);
        int s1 = __ldg(&column_index[e + 1]);
        float2 v0 = ((const float2*)(g_h + (size_t)s0 * C))[lane];
        float2 v1 = ((const float2*)(g_h + (size_t)s1 * C))[lane];
        ax += v0.x + v1.x;
        ay += v0.y + v1.y;
    }
    if (e < end) {
        int s0 = __ldg(&column_index[e]);
        float2 v0 = ((const float2*)(g_h + (size_t)s0 * C))[lane];
        ax += v0.x;
        ay += v0.y;
    }

    const float d = degrees[gwarp];
    const float2 b = ((const float2*)bias)[lane];
    float2 o;
    o.x = ax * d + b.x;
    o.y = ay * d + b.y;
    ((float2*)(out + (size_t)gwarp * C))[lane] = o;
}

// ---------------------------------------------------------------------------
extern "C" void kernel_launch(void* const* d_in, const int* in_sizes, int n_in,
                              void* d_out, int out_size) {
    const float* x            = (const float*)d_in[0];   // [N_NODES, 64]
    const float* weight       = (const float*)d_in[1];   // [64, 64]
    const float* bias         = (const float*)d_in[2];   // [64]
    const int*   column_index = (const int*)d_in[3];     // [N_EDGES]
    const int*   row_index    = (const int*)d_in[4];     // [N_EDGES] sorted
    const float* degrees      = (const float*)d_in[5];   // [N_NODES]
    float* out = (float*)d_out;                          // [N_NODES, 64]

    // 1) h = x @ W
    int gemm_blocks = (N_NODES + 63) / 64;
    gemm64_kernel<<<gemm_blocks, 256>>>(x, weight);

    // 2) CSR row pointers from sorted row_index
    rowptr_kernel<<<(N_NODES + 1 + 255) / 256, 256>>>(row_index);

    // 3) gather + segment-sum + degree*agg + bias
    int agg_blocks = (N_NODES * 32 + 255) / 256;  // one warp per node
    agg_kernel<<<agg_blocks, 256>>>(column_index, degrees, bias, out);
}

// round 2
// speedup vs baseline: 1.1394x; 1.1394x over previous
#include <cuda_runtime.h>
#include <cuda_bf16.h>

#define N_NODES 100000
#define N_EDGES 1600000
#define C 64

// Scratch: transformed features h = x @ W, and CSR row pointers.
__device__ float g_h[(size_t)N_NODES * C];
__device__ int g_row_ptr[N_NODES + 1];

static __device__ __forceinline__ unsigned long long dup_f32x2(float x) {
    unsigned long long r;
    asm("mov.b64 %0, {%1, %1};" : "=l"(r) : "f"(x));
    return r;
}
static __device__ __forceinline__ float2 unpack_f32x2(unsigned long long v) {
    float2 r;
    asm("mov.b64 {%0, %1}, %2;" : "=f"(r.x), "=f"(r.y) : "l"(v));
    return r;
}
#define FMA2(acc, a, b) asm("fma.rn.f32x2 %0, %1, %2, %0;" : "+l"(acc) : "l"(a), "l"(b))

// ---------------------------------------------------------------------------
// Kernel 1: h = x @ W
// 128 rows per block, 128 threads. Thread (warp w, lane l) computes rows
// {l, l+32, l+64, l+96} x cols [w*16, w*16+16) in 32 packed f32x2 accumulators.
// Per k: 4 broadcast LDS.128 (W) + 4 conflict-free LDS (x) feed 32 FFMA2.
// ---------------------------------------------------------------------------
__global__ __launch_bounds__(128) void gemm_kernel(const float* __restrict__ x,
                                                   const float* __restrict__ w) {
    __shared__ float ws[64 * 64];    // 16 KB, W row-major [k][n]
    __shared__ float xs[128 * 64];   // 32 KB, XOR-swizzled x tile (row-major)

    const int tid = threadIdx.x;
    const int w_id = tid >> 5;       // warp -> 16-col slice
    const int l = tid & 31;          // lane -> row set
    const long row0 = (long)blockIdx.x * 128;

    // Load W (1024 float4) cooperatively.
    const float4* w4 = (const float4*)w;
    float4* ws4 = (float4*)ws;
#pragma unroll
    for (int i = 0; i < 8; i++) ws4[tid + i * 128] = w4[tid + i * 128];

    // Load x tile: 2048 float4 coalesced, scalar XOR-swizzled stores.
#pragma unroll
    for (int i = 0; i < 16; i++) {
        int f4 = i * 128 + tid;
        int r = f4 >> 4, c4 = f4 & 15;
        long gr = row0 + r;
        float4 v = make_float4(0.f, 0.f, 0.f, 0.f);
        if (gr < N_NODES) v = ((const float4*)x)[gr * 16 + c4];
        int sw = r & 31;
        float* base = xs + r * 64;
        base[(c4 * 4 + 0) ^ sw] = v.x;
        base[(c4 * 4 + 1) ^ sw] = v.y;
        base[(c4 * 4 + 2) ^ sw] = v.z;
        base[(c4 * 4 + 3) ^ sw] = v.w;
    }
    __syncthreads();

    unsigned long long acc[4][8];
#pragma unroll
    for (int m = 0; m < 4; m++)
#pragma unroll
        for (int j = 0; j < 8; j++) acc[m][j] = 0ull;

#pragma unroll 4
    for (int k = 0; k < 64; k++) {
        // x values for this thread's 4 rows (rows ≡ l mod 32 → swizzle key = l)
        unsigned long long x2[4];
#pragma unroll
        for (int m = 0; m < 4; m++)
            x2[m] = dup_f32x2(xs[(m * 32 + l) * 64 + (k ^ l)]);

        // W row chunk: 16 floats, 4 broadcast LDS.128
        const ulonglong2* wr = (const ulonglong2*)(ws + k * 64 + w_id * 16);
        ulonglong2 wv0 = wr[0], wv1 = wr[1], wv2 = wr[2], wv3 = wr[3];

#pragma unroll
        for (int m = 0; m < 4; m++) {
            FMA2(acc[m][0], x2[m], wv0.x);
            FMA2(acc[m][1], x2[m], wv0.y);
            FMA2(acc[m][2], x2[m], wv1.x);
            FMA2(acc[m][3], x2[m], wv1.y);
            FMA2(acc[m][4], x2[m], wv2.x);
            FMA2(acc[m][5], x2[m], wv2.y);
            FMA2(acc[m][6], x2[m], wv3.x);
            FMA2(acc[m][7], x2[m], wv3.y);
        }
    }

    // Epilogue: stage through smem (reuse xs) so the global store is coalesced.
    __syncthreads();
    float4* xs4 = (float4*)xs;
#pragma unroll
    for (int m = 0; m < 4; m++) {
        int row = m * 32 + l;
        int rsw = row & 15;
#pragma unroll
        for (int j4 = 0; j4 < 4; j4++) {
            float2 a = unpack_f32x2(acc[m][2 * j4]);
            float2 b = unpack_f32x2(acc[m][2 * j4 + 1]);
            xs4[row * 16 + ((w_id * 4 + j4) ^ rsw)] = make_float4(a.x, a.y, b.x, b.y);
        }
    }
    __syncthreads();
#pragma unroll
    for (int i = 0; i < 16; i++) {
        int f4 = i * 128 + tid;
        int row = f4 >> 4, c4 = f4 & 15;
        long gr = row0 + row;
        if (gr < N_NODES)
            ((float4*)g_h)[gr * 16 + c4] = xs4[row * 16 + (c4 ^ (row & 15))];
    }
}

// ---------------------------------------------------------------------------
// Kernel 2: row_ptr[n] = lower_bound(row_index, n)  (row_index is sorted)
// ---------------------------------------------------------------------------
__global__ __launch_bounds__(256) void rowptr_kernel(const int* __restrict__ row_index) {
    int n = blockIdx.x * blockDim.x + threadIdx.x;
    if (n > N_NODES) return;
    int lo = 0, hi = N_EDGES;
    while (lo < hi) {
        int mid = (lo + hi) >> 1;
        if (row_index[mid] < n) lo = mid + 1;
        else hi = mid;
    }
    g_row_ptr[n] = lo;
}

// ---------------------------------------------------------------------------
// Kernel 3: warp-per-node segment sum over gathered h rows, fused
// degree scale + bias. No atomics (CSR segments). float2 per lane.
// ---------------------------------------------------------------------------
__global__ __launch_bounds__(256) void agg_kernel(const int* __restrict__ column_index,
                                                  const float* __restrict__ degrees,
                                                  const float* __restrict__ bias,
                                                  float* __restrict__ out) {
    const int gwarp = (blockIdx.x * blockDim.x + threadIdx.x) >> 5;
    const int lane = threadIdx.x & 31;
    if (gwarp >= N_NODES) return;

    const int start = g_row_ptr[gwarp];
    const int end = g_row_ptr[gwarp + 1];

    float ax = 0.f, ay = 0.f;

    int e = start;
    for (; e + 3 < end; e += 4) {
        int s0 = __ldg(&column_index[e]);
        int s1 = __ldg(&column_index[e + 1]);
        int s2 = __ldg(&column_index[e + 2]);
        int s3 = __ldg(&column_index[e + 3]);
        float2 v0 = ((const float2*)(g_h + (size_t)s0 * C))[lane];
        float2 v1 = ((const float2*)(g_h + (size_t)s1 * C))[lane];
        float2 v2 = ((const float2*)(g_h + (size_t)s2 * C))[lane];
        float2 v3 = ((const float2*)(g_h + (size_t)s3 * C))[lane];
        ax += (v0.x + v1.x) + (v2.x + v3.x);
        ay += (v0.y + v1.y) + (v2.y + v3.y);
    }
    for (; e < end; e++) {
        int s0 = __ldg(&column_index[e]);
        float2 v0 = ((const float2*)(g_h + (size_t)s0 * C))[lane];
        ax += v0.x;
        ay += v0.y;
    }

    const float d = degrees[gwarp];
    const float2 b = ((const float2*)bias)[lane];
    float2 o;
    o.x = ax * d + b.x;
    o.y = ay * d + b.y;
    ((float2*)(out + (size_t)gwarp * C))[lane] = o;
}

// ---------------------------------------------------------------------------
extern "C" void kernel_launch(void* const* d_in, const int* in_sizes, int n_in,
                              void* d_out, int out_size) {
    const float* x            = (const float*)d_in[0];   // [N_NODES, 64]
    const float* weight       = (const float*)d_in[1];   // [64, 64]
    const float* bias         = (const float*)d_in[2];   // [64]
    const int*   column_index = (const int*)d_in[3];     // [N_EDGES]
    const int*   row_index    = (const int*)d_in[4];     // [N_EDGES] sorted
    const float* degrees      = (const float*)d_in[5];   // [N_NODES]
    float* out = (float*)d_out;                          // [N_NODES, 64]

    // 1) CSR row pointers (independent of GEMM; tiny)
    rowptr_kernel<<<(N_NODES + 1 + 255) / 256, 256>>>(row_index);

    // 2) h = x @ W
    gemm_kernel<<<(N_NODES + 127) / 128, 128>>>(x, weight);

    // 3) gather + segment-sum + degree*agg + bias
    agg_kernel<<<(N_NODES * 32 + 255) / 256, 256>>>(column_index, degrees, bias, out);
}